// round 2
// baseline (speedup 1.0000x reference)
#include <cuda_runtime.h>

// VectorP1FunctionSpace: evaluate two P1 FEM interpolants (weights wx, wy) on a
// structured 32x32 triangulation of [0,1]^2 at query points x, via the exact
// analytic barycentric form (relu/min hat construction == barycentric coords).
//
// R2: latency/overhead-bound (DRAM 0.4%, issue 3.8%). Spread grid over 128 SMs
// (128 blocks x 128 threads), branchless triangle select to drop BSSY/BSYNC.

#define NXY    32
#define NYP1   33

__global__ __launch_bounds__(128, 1)
void vp1_eval_kernel(const float2* __restrict__ x,
                     const float*  __restrict__ wx,
                     const float*  __restrict__ wy,
                     float2*       __restrict__ out,
                     int total)
{
    int idx = blockIdx.x * blockDim.x + threadIdx.x;
    if (idx >= total) return;

    float2 p = x[idx];
    float sx = p.x * (float)NXY;
    float sy = p.y * (float)NXY;

    int i = (int)floorf(sx);
    int j = (int)floorf(sy);
    i = min(max(i, 0), NXY - 1);
    j = min(max(j, 0), NXY - 1);

    float fx = sx - (float)i;
    float fy = sy - (float)j;

    int v00 = i * NYP1 + j;       // (i,   j)
    int v11 = v00 + NYP1 + 1;     // (i+1, j+1)

    // Branchless: lower-right tri (v00,v10,v11) when fx>=fy with (1-fx, fx-fy, fy),
    // else upper-left tri (v00,v11,v01) with (1-fy, fx, fy-fx).
    bool  lower = (fx >= fy);
    float fmax_ = lower ? fx : fy;
    int   vb    = lower ? (v00 + NYP1) : v11;   // v10 : v11
    int   vc    = lower ? v11 : (v00 + 1);      // v11 : v01
    float l0    = 1.0f - fmax_;
    float l1    = lower ? (fx - fy) : fx;
    float l2    = lower ? fy : (fy - fx);

    // 6 independent scattered loads (L1/L2-resident weights)
    float wa_x = __ldg(&wx[v00]);
    float wb_x = __ldg(&wx[vb]);
    float wc_x = __ldg(&wx[vc]);
    float wa_y = __ldg(&wy[v00]);
    float wb_y = __ldg(&wy[vb]);
    float wc_y = __ldg(&wy[vc]);

    float ox = fmaf(l0, wa_x, fmaf(l1, wb_x, l2 * wc_x));
    float oy = fmaf(l0, wa_y, fmaf(l1, wb_y, l2 * wc_y));

    out[idx] = make_float2(ox, oy);
}

extern "C" void kernel_launch(void* const* d_in, const int* in_sizes, int n_in,
                              void* d_out, int out_size)
{
    const float* x  = (const float*)d_in[0];   // [B, N, 2]
    // d_in[1] = W [V,6,2], d_in[2] = c [V,6]  -- unused (analytic form)
    const float* wx = (const float*)d_in[3];   // [V]
    const float* wy = (const float*)d_in[4];   // [V]
    float* out = (float*)d_out;                // [B, N, 2]

    int total = out_size / 2;                  // B*N query points

    int threads = 128;
    int blocks  = (total + threads - 1) / threads;   // 128 blocks for 16384 pts
    vp1_eval_kernel<<<blocks, threads>>>((const float2*)x, wx, wy,
                                         (float2*)out, total);
}

// round 3
// speedup vs baseline: 1.0388x; 1.0388x over previous
#include <cuda_runtime.h>

// VectorP1FunctionSpace: evaluate two P1 FEM interpolants (wx, wy) on a
// structured 32x32 triangulation of [0,1]^2 via the exact analytic barycentric
// form (the reference's relu/min hat construction == barycentric coords).
//
// R3: overhead + latency-chain bound. 2 points/thread (float4 I/O, 8192
// threads), and off-chain L1 prefetch of the weight tables so the dependent
// weight loads (issued only after x arrives) hit L1 (~39cyc) instead of L2
// (~234cyc). L1 is flushed every launch, so this pays on every graph replay.

#define NXY    32
#define NYP1   33

__device__ __forceinline__ void eval_point(float px, float py,
                                           const float* __restrict__ wx,
                                           const float* __restrict__ wy,
                                           float& ox, float& oy)
{
    float sx = px * (float)NXY;
    float sy = py * (float)NXY;

    int i = (int)floorf(sx);
    int j = (int)floorf(sy);
    i = min(max(i, 0), NXY - 1);
    j = min(max(j, 0), NXY - 1);

    float fx = sx - (float)i;
    float fy = sy - (float)j;

    int v00 = i * NYP1 + j;
    int v11 = v00 + NYP1 + 1;

    // lower-right tri (v00,v10,v11): (1-fx, fx-fy, fy); else (v00,v11,v01): (1-fy, fx, fy-fx)
    bool  lower = (fx >= fy);
    float fm    = lower ? fx : fy;
    int   vb    = lower ? (v00 + NYP1) : v11;
    int   vc    = lower ? v11 : (v00 + 1);
    float l0    = 1.0f - fm;
    float l1    = lower ? (fx - fy) : fx;
    float l2    = lower ? fy : (fy - fx);

    float wa_x = __ldg(&wx[v00]);
    float wb_x = __ldg(&wx[vb]);
    float wc_x = __ldg(&wx[vc]);
    float wa_y = __ldg(&wy[v00]);
    float wb_y = __ldg(&wy[vb]);
    float wc_y = __ldg(&wy[vc]);

    ox = fmaf(l0, wa_x, fmaf(l1, wb_x, l2 * wc_x));
    oy = fmaf(l0, wa_y, fmaf(l1, wb_y, l2 * wc_y));
}

__global__ void vp1_eval_kernel(const float4* __restrict__ x,
                                const float*  __restrict__ wx,
                                const float*  __restrict__ wy,
                                float4*       __restrict__ out,
                                int npairs)
{
    int idx = blockIdx.x * blockDim.x + threadIdx.x;
    if (idx >= npairs) return;

    // Dependent load: two query points (16 bytes).
    float4 p = x[idx];

    // Off-chain prefetch: warm L1 with the weight tables while x is in flight.
    // 8192 threads, pf in [0,1088] covers all vertices. Results discarded;
    // asm volatile keeps the loads, no data dependency on the output path.
    {
        int pf = idx & 2047;
        pf = min(pf, 1088);
        float t0, t1;
        asm volatile("ld.global.nc.f32 %0, [%1];" : "=f"(t0) : "l"(wx + pf));
        asm volatile("ld.global.nc.f32 %0, [%1];" : "=f"(t1) : "l"(wy + pf));
    }

    float4 r;
    eval_point(p.x, p.y, wx, wy, r.x, r.y);
    eval_point(p.z, p.w, wx, wy, r.z, r.w);

    out[idx] = r;
}

extern "C" void kernel_launch(void* const* d_in, const int* in_sizes, int n_in,
                              void* d_out, int out_size)
{
    const float* x  = (const float*)d_in[0];   // [B, N, 2]
    // d_in[1] = W [V,6,2], d_in[2] = c [V,6]  -- unused (analytic form)
    const float* wx = (const float*)d_in[3];   // [V]
    const float* wy = (const float*)d_in[4];   // [V]
    float* out = (float*)d_out;                // [B, N, 2]

    int npairs = out_size / 4;                 // 2 points (4 floats) per thread

    int threads = 128;
    int blocks  = (npairs + threads - 1) / threads;   // 64 CTAs for 8192 pairs
    vp1_eval_kernel<<<blocks, threads>>>((const float4*)x, wx, wy,
                                         (float4*)out, npairs);
}